// round 12
// baseline (speedup 1.0000x reference)
#include <cuda_runtime.h>
#include <math.h>

#define Bb   16
#define Nn   1024
#define DIN  32
#define DZ   64
#define DH   64
#define Ff   3
#define Pp   19
#define PPAD 20
#define NEDGE 171
#define ITERS 50
#define ALPHAc 0.1f
#define INV_SCALE (19.0f/1024.0f)
#define SOLV_T 704

// ---------------- device scratch (static; no allocations) ----------------
__device__ __align__(16) float2 g_wpair[(size_t)Bb*Ff*Nn*PPAD]; // {w,w} pairs for FFMA2 (stage1)
__device__ __align__(16) float  g_wc[(size_t)Bb*Ff*Nn*PPAD];    // compact weights (stage2/ufine)
__device__ __align__(16) float  g_t[(size_t)192*Pp*Nn];         // stage-1 partials
__device__ __align__(16) float  g_khat[2*Bb*Ff*Pp*Pp];          // [mat][b][f][p][q]
__device__ __align__(16) float  g_zpart[Bb*8*DZ];               // per-block z partial sums
__device__ __align__(16) float  g_flpart[Bb*8*64];              // per-block f_latent partials (57 used)
__device__ __align__(16) float  g_uhat[Bb*64];

// packed f32x2 FMA (Blackwell FFMA2)
__device__ __forceinline__ unsigned long long ffma2(unsigned long long a,
                                                    unsigned long long b,
                                                    unsigned long long c) {
    unsigned long long d;
    asm("fma.rn.f32x2 %0, %1, %2, %3;" : "=l"(d) : "l"(a), "l"(b), "l"(c));
    return d;
}
__device__ __forceinline__ float2 ull2f2(unsigned long long v) {
    float2 r;
    asm("mov.b64 {%0,%1}, %2;" : "=f"(r.x), "=f"(r.y) : "l"(v));
    return r;
}
__device__ __forceinline__ unsigned long long packdup(float v) {
    unsigned long long r;
    asm("mov.b64 %0, {%1,%1};" : "=l"(r) : "f"(v));
    return r;
}
__device__ __forceinline__ unsigned long long pack2(float a, float b) {
    unsigned long long r;
    asm("mov.b64 %0, {%1,%2};" : "=l"(r) : "f"(a), "f"(b));
    return r;
}
__device__ __forceinline__ float warp_sum(float v) {
    v += __shfl_xor_sync(0xffffffffu, v, 16);
    v += __shfl_xor_sync(0xffffffffu, v, 8);
    v += __shfl_xor_sync(0xffffffffu, v, 4);
    v += __shfl_xor_sync(0xffffffffu, v, 2);
    v += __shfl_xor_sync(0xffffffffu, v, 1);
    return v;
}

// ---------------- kernel 1: encoder + POU softmax + fused partial reductions ----------------
__global__ __launch_bounds__(128) void k_encode(
    const float* __restrict__ tok, const int* __restrict__ dn,
    const float* __restrict__ bv,
    const float* __restrict__ W_enc, const float* __restrict__ b_enc,
    const float* __restrict__ W_src, const float* __restrict__ b_src,
    const float* __restrict__ W_pou)
{
    __shared__ float sWe[DIN*DZ];
    __shared__ float sWp[DZ*57];
    __shared__ float sWs[DZ*Ff];
    __shared__ float sbe[DZ];
    __shared__ float sbs[Ff];
    __shared__ int   sdn[64];
    __shared__ float sbv[64*Ff];
    __shared__ float sW4[4][DZ];     // warp partials for z-mean
    __shared__ float sFl[4][Pp];     // warp partials for f_latent (per f)

    int b = blockIdx.y;
    int tid = threadIdx.x;
    int wid = tid >> 5, lane = tid & 31;
    for (int i = tid; i < DIN*DZ; i += 128) sWe[i] = W_enc[i];
    for (int i = tid; i < DZ*57;  i += 128) sWp[i] = W_pou[i];
    for (int i = tid; i < DZ*Ff;  i += 128) sWs[i] = W_src[i];
    if (tid < DZ) sbe[tid] = b_enc[tid];
    if (tid < Ff) sbs[tid] = b_src[tid];
    if (tid < 64) sdn[tid] = dn[b*64 + tid];
    for (int i = tid; i < 64*Ff; i += 128) sbv[i] = bv[b*64*Ff + i];
    __syncthreads();

    int n = blockIdx.x*128 + tid;

    float x[DIN];
    const float4* xp = (const float4*)(tok + ((size_t)b*Nn + n)*DIN);
    #pragma unroll
    for (int i = 0; i < DIN/4; i++) {
        float4 v = xp[i];
        x[4*i] = v.x; x[4*i+1] = v.y; x[4*i+2] = v.z; x[4*i+3] = v.w;
    }

    float z[DZ];
    #pragma unroll
    for (int d = 0; d < DZ; d++) z[d] = sbe[d];
    for (int k = 0; k < DIN; k++) {
        float xv = x[k];
        const float* wr = sWe + k*DZ;
        #pragma unroll
        for (int d = 0; d < DZ; d++) z[d] += xv * wr[d];
    }
    #pragma unroll
    for (int d = 0; d < DZ; d++) z[d] = tanhf(z[d]);

    // z-mean partial (deterministic: fixed warp/block reduction order)
    #pragma unroll
    for (int d = 0; d < DZ; d++) {
        float v = warp_sum(z[d]);
        if (lane == 0) sW4[wid][d] = v;
    }
    __syncthreads();
    if (tid < DZ)
        g_zpart[((size_t)b*8 + blockIdx.x)*DZ + tid] =
            sW4[0][tid] + sW4[1][tid] + sW4[2][tid] + sW4[3][tid];

    // f_full
    float ffull[Ff];
    #pragma unroll
    for (int f = 0; f < Ff; f++) {
        float s = sbs[f];
        for (int d = 0; d < DZ; d++) s += z[d]*sWs[d*Ff + f];
        ffull[f] = s;
    }

    // boundary value scatter (last occurrence wins, matching JAX .set)
    float bvv[Ff] = {0.f, 0.f, 0.f};
    for (int k = 0; k < 64; k++) {
        if (sdn[k] == n) {
            bvv[0] = sbv[k*Ff]; bvv[1] = sbv[k*Ff+1]; bvv[2] = sbv[k*Ff+2];
        }
    }

    // softmax over P per field + weight stores + f_latent partials
    for (int f = 0; f < Ff; f++) {
        float lg[Pp];
        #pragma unroll
        for (int p = 0; p < Pp; p++) {
            float s = 0.f;
            for (int d = 0; d < DZ; d++) s += z[d]*sWp[d*57 + p*Ff + f];
            lg[p] = s;
        }
        lg[16] += bvv[f]; lg[17] += bvv[f]; lg[18] += bvv[f];
        float m = lg[0];
        #pragma unroll
        for (int p = 1; p < Pp; p++) m = fmaxf(m, lg[p]);
        float s = 0.f;
        #pragma unroll
        for (int p = 0; p < Pp; p++) { lg[p] = __expf(lg[p]-m); s += lg[p]; }
        float inv = 1.f/s;
        float2* wp = g_wpair + ((size_t)(b*Ff + f)*Nn + n)*PPAD;
        float*  wc = g_wc    + ((size_t)(b*Ff + f)*Nn + n)*PPAD;
        #pragma unroll
        for (int p = 0; p < Pp; p++) {
            float w = lg[p]*inv;
            lg[p] = w;
            wp[p] = make_float2(w, w);
            wc[p] = w;
        }
        // f_latent partial for this field
        __syncthreads();
        #pragma unroll
        for (int p = 0; p < Pp; p++) {
            float v = warp_sum(lg[p]*ffull[f]);
            if (lane == 0) sFl[wid][p] = v;
        }
        __syncthreads();
        if (tid < Pp)
            g_flpart[((size_t)b*8 + blockIdx.x)*64 + tid*Ff + f] =
                sFl[0][tid] + sFl[1][tid] + sFl[2][tid] + sFl[3][tid];
    }
}

// ------------- kernel 2: stage-1 projection  t[p,j] = sum_i W[p,i]*A[i,j] -------------
__global__ __launch_bounds__(64) void k_stage1(const float* __restrict__ Kl,
                                               const float* __restrict__ Ml)
{
    int bf   = blockIdx.y;
    int mat  = blockIdx.z >> 1;
    int half = blockIdx.z & 1;
    int j0   = blockIdx.x*256 + threadIdx.x*4;

    const float* src = (mat ? Ml : Kl) + (size_t)bf*Nn*Nn;
    const unsigned long long* wsrc =
        (const unsigned long long*)(g_wpair + (size_t)bf*Nn*PPAD);

    __shared__ __align__(16) unsigned long long sw[32*PPAD];

    unsigned long long acc[2*Pp];
    #pragma unroll
    for (int i = 0; i < 2*Pp; i++) acc[i] = 0ull;

    for (int ic = 0; ic < 16; ic++) {
        int ib = half*512 + ic*32;
        const unsigned long long* g = wsrc + (size_t)ib*PPAD;
        for (int idx = threadIdx.x; idx < 32*PPAD; idx += 64) sw[idx] = g[idx];
        __syncthreads();
        const float* kptr = src + (size_t)ib*Nn + j0;
        #pragma unroll 4
        for (int ii = 0; ii < 32; ii++) {
            float4 kv = *(const float4*)kptr;
            unsigned long long kx = pack2(kv.x, kv.y);
            unsigned long long ky = pack2(kv.z, kv.w);
            kptr += Nn;
            const unsigned long long* wrow = sw + ii*PPAD;
            #pragma unroll
            for (int p = 0; p < Pp; p++) {
                unsigned long long w = wrow[p];
                acc[2*p]   = ffma2(w, kx, acc[2*p]);
                acc[2*p+1] = ffma2(w, ky, acc[2*p+1]);
            }
        }
        __syncthreads();
    }

    float* tp = g_t + ((size_t)((bf*2 + mat)*2 + half))*Pp*Nn;
    #pragma unroll
    for (int p = 0; p < Pp; p++) {
        float2 a0 = ull2f2(acc[2*p]);
        float2 a1 = ull2f2(acc[2*p+1]);
        *(float4*)(tp + p*Nn + j0) = make_float4(a0.x, a0.y, a1.x, a1.y);
    }
}

// ------------- stage-2: K_hat[p,q] = (t W^T)/scale + Dirichlet rows -------------
__global__ __launch_bounds__(384) void k_stage2()
{
    int bf = blockIdx.x;
    int mat = blockIdx.y;
    __shared__ float tS[Pp][129];
    __shared__ float wS[128*PPAD];
    int t = threadIdx.x;
    int p = t % Pp, q = t / Pp;
    bool act = (t < Pp*Pp);
    float acc = 0.f;
    const float* t0 = g_t + (size_t)((bf*2 + mat)*2)*Pp*Nn;
    const float* t1 = t0 + Pp*Nn;
    const float* wsrc0 = g_wc + (size_t)bf*Nn*PPAD;
    for (int jc = 0; jc < 8; jc++) {
        for (int idx = t; idx < Pp*128; idx += 384) {
            int pp = idx >> 7, jj = idx & 127;
            tS[pp][jj] = t0[pp*Nn + jc*128 + jj] + t1[pp*Nn + jc*128 + jj];
        }
        const float* wsrc = wsrc0 + (size_t)jc*128*PPAD;
        for (int idx = t; idx < 128*PPAD; idx += 384) wS[idx] = wsrc[idx];
        __syncthreads();
        if (act) {
            #pragma unroll 8
            for (int jj = 0; jj < 128; jj++) acc += tS[p][jj]*wS[jj*PPAD + q];
        }
        __syncthreads();
    }
    if (act) {
        float v = acc * INV_SCALE;
        if (p >= Pp-3) v = (p == q) ? 1.f : 0.f;
        g_khat[((size_t)mat*Bb*Ff + bf)*Pp*Pp + p*Pp + q] = v;
    }
}

// ------------- solver: prologue reductions + 50 damped fixed-point iterations -------------
// 704 threads: flux threads t = edge*4 + quarter, each quarter handles 16 h
// values as 8 packed f32x2 h-pairs (FFMA2); partials combined via shfl.
__global__ __launch_bounds__(SOLV_T) void k_solver(const float* __restrict__ u_init,
                                                   const float* __restrict__ Wf1,
                                                   const float* __restrict__ Wf2,
                                                   const float* __restrict__ Wz,
                                                   const float* __restrict__ bfv)
{
    int b = blockIdx.x, t = threadIdx.x;
    __shared__ float Ks[Ff*Pp*Pp];
    __shared__ __align__(16) float w1p[32*16]; // per h-pair: A0..A5 pairs, zp pair, pad2
    __shared__ __align__(16) float w2p[32*8];  // per h-pair: C0,C1,C2 pairs, pad2
    __shared__ float srcs[64];
    __shared__ float flux[NEDGE*4];
    __shared__ float ua[64], ub[64];
    __shared__ float mz[DZ];
    __shared__ float sfl[64];

    for (int i = t; i < Ff*Pp*Pp; i += SOLV_T)
        Ks[i] = g_khat[(size_t)b*Ff*Pp*Pp + i];
    if (t < DH) {  // interleave Wf1/Wf2 as h-pair lanes
        int hp = t >> 1, par = t & 1;
        w1p[hp*16 + 0  + par] = Wf1[0*DH + t];
        w1p[hp*16 + 2  + par] = Wf1[1*DH + t];
        w1p[hp*16 + 4  + par] = Wf1[2*DH + t];
        w1p[hp*16 + 6  + par] = Wf1[3*DH + t];
        w1p[hp*16 + 8  + par] = Wf1[4*DH + t];
        w1p[hp*16 + 10 + par] = Wf1[5*DH + t];
        w1p[hp*16 + 14 + par] = 0.f;
        w2p[hp*8 + 0 + par] = Wf2[t*Ff + 0];
        w2p[hp*8 + 2 + par] = Wf2[t*Ff + 1];
        w2p[hp*8 + 4 + par] = Wf2[t*Ff + 2];
        w2p[hp*8 + 6 + par] = 0.f;
    }
    if (t < Pp*Ff) ua[t] = u_init[b*Pp*Ff + t];
    // reduce z-mean and f_latent partials (deterministic fixed order)
    if (t < DZ) {
        float s = 0.f;
        #pragma unroll
        for (int k = 0; k < 8; k++) s += g_zpart[((size_t)b*8 + k)*DZ + t];
        mz[t] = s * (1.f/Nn);
    } else if (t >= 64 && t < 64 + Pp*Ff) {
        int k = t - 64;
        float s = 0.f;
        #pragma unroll
        for (int j = 0; j < 8; j++) s += g_flpart[((size_t)b*8 + j)*64 + k];
        sfl[k] = s * INV_SCALE;
    }
    __syncthreads();

    if (t < DH) {  // zp = mean(z) @ Wz + bf  -> pair slot 12/13 of w1p
        float a = bfv[t];
        #pragma unroll 8
        for (int d = 0; d < DZ; d++) a += mz[d]*Wz[d*DH + t];
        w1p[(t >> 1)*16 + 12 + (t & 1)] = a;
    } else if (t >= 64 && t < 64 + Pp*Ff) {  // src_term = M_hat @ f_latent
        int k = t - 64;
        int p = k / Ff, f = k % Ff;
        const float* mrow = g_khat + ((size_t)Bb*Ff + b*Ff + f)*Pp*Pp + p*Pp;
        float s = 0.f;
        #pragma unroll
        for (int q = 0; q < Pp; q++) s += mrow[q]*sfl[q*Ff + f];
        srcs[k] = s;
    }

    // flux-thread mapping: keep ALL warps converged (clamp e, guard the write)
    int e_raw = t >> 2;
    int qt = t & 3;
    int e = (e_raw < NEDGE) ? e_raw : 0;
    int ei, ej;
    {
        int ee = e, a = 0;
        while (ee >= Pp-1-a) { ee -= (Pp-1-a); a++; }
        ei = a; ej = a + 1 + ee;
    }
    const unsigned long long* w1u = ((const unsigned long long*)w1p) + qt*64;
    const unsigned long long* w2u = ((const unsigned long long*)w2p) + qt*32;
    __syncthreads();

    float* cur = ua; float* nxt = ub;
    for (int it = 0; it < ITERS; it++) {
        {
            unsigned long long up0 = packdup(cur[ei*Ff+0]);
            unsigned long long up1 = packdup(cur[ei*Ff+1]);
            unsigned long long up2 = packdup(cur[ei*Ff+2]);
            unsigned long long up3 = packdup(cur[ej*Ff+0]);
            unsigned long long up4 = packdup(cur[ej*Ff+1]);
            unsigned long long up5 = packdup(cur[ej*Ff+2]);
            unsigned long long acc0 = 0ull, acc1 = 0ull, acc2 = 0ull;
            #pragma unroll
            for (int hp = 0; hp < 8; hp++) {
                const unsigned long long* r1 = w1u + hp*8;
                unsigned long long s = r1[6];            // zp pair
                s = ffma2(up0, r1[0], s);
                s = ffma2(up1, r1[1], s);
                s = ffma2(up2, r1[2], s);
                s = ffma2(up3, r1[3], s);
                s = ffma2(up4, r1[4], s);
                s = ffma2(up5, r1[5], s);
                float2 sv = ull2f2(s);
                float r0, r1f;
                asm("tanh.approx.f32 %0, %1;" : "=f"(r0)  : "f"(sv.x));
                asm("tanh.approx.f32 %0, %1;" : "=f"(r1f) : "f"(sv.y));
                unsigned long long rp = pack2(r0, r1f);
                const unsigned long long* r2 = w2u + hp*4;
                acc0 = ffma2(rp, r2[0], acc0);
                acc1 = ffma2(rp, r2[1], acc1);
                acc2 = ffma2(rp, r2[2], acc2);
            }
            float2 f0 = ull2f2(acc0), f1 = ull2f2(acc1), f2 = ull2f2(acc2);
            float a0 = f0.x + f0.y, a1 = f1.x + f1.y, a2 = f2.x + f2.y;
            // reduce across the 4 quarter-threads (nibble-aligned lanes)
            a0 += __shfl_xor_sync(0xffffffffu, a0, 1);
            a0 += __shfl_xor_sync(0xffffffffu, a0, 2);
            a1 += __shfl_xor_sync(0xffffffffu, a1, 1);
            a1 += __shfl_xor_sync(0xffffffffu, a1, 2);
            a2 += __shfl_xor_sync(0xffffffffu, a2, 1);
            a2 += __shfl_xor_sync(0xffffffffu, a2, 2);
            if (qt == 0 && e_raw < NEDGE) {
                flux[e*4+0] = a0; flux[e*4+1] = a1; flux[e*4+2] = a2;
            }
        }
        __syncthreads();
        if (t < Pp*Ff) {
            int p = t / Ff, f = t % Ff;
            const float* kr = Ks + f*Pp*Pp + p*Pp;
            float diff = 0.f;
            #pragma unroll
            for (int q = 0; q < Pp; q++) diff += kr[q]*cur[q*Ff + f];
            float ft = 0.f;
            for (int q = 0; q < p; q++) {           // p == ej -> +flux
                int ee = q*(Pp-1) - (q*(q-1))/2 + (p - q - 1);
                ft += flux[ee*4 + f];
            }
            for (int q = p+1; q < Pp; q++) {        // p == ei -> -flux
                int ee = p*(Pp-1) - (p*(p-1))/2 + (q - p - 1);
                ft -= flux[ee*4 + f];
            }
            float r = diff - srcs[t] - ft;
            if (p >= Pp-3) r = cur[t] - ((p == Pp-3) ? 1.f : 0.f);
            nxt[t] = cur[t] - ALPHAc*r;
        }
        __syncthreads();
        float* tmp = cur; cur = nxt; nxt = tmp;
    }
    if (t < Pp*Ff) g_uhat[b*64 + t] = cur[t];
}

// ------------- u_fine = W^T u_coarse (compact weights, vectorized) -------------
__global__ __launch_bounds__(128) void k_ufine(float* __restrict__ out)
{
    int b = blockIdx.y;
    int tid = threadIdx.x;
    int n = blockIdx.x*128 + tid;
    __shared__ float us[64];
    __shared__ __align__(16) float so[384];
    if (tid < 64) us[tid] = g_uhat[b*64 + tid];
    __syncthreads();
    float o[Ff];
    #pragma unroll
    for (int f = 0; f < Ff; f++) {
        const float4* wv = (const float4*)(g_wc + ((size_t)(b*Ff + f)*Nn + n)*PPAD);
        float acc = 0.f;
        #pragma unroll
        for (int k = 0; k < 5; k++) {
            float4 w4 = wv[k];
            int p0 = 4*k;
            acc += w4.x*us[p0*Ff + f];
            if (p0+1 < Pp) acc += w4.y*us[(p0+1)*Ff + f];
            if (p0+2 < Pp) acc += w4.z*us[(p0+2)*Ff + f];
            if (p0+3 < Pp) acc += w4.w*us[(p0+3)*Ff + f];
        }
        o[f] = acc;
    }
    so[tid*3+0] = o[0]; so[tid*3+1] = o[1]; so[tid*3+2] = o[2];
    __syncthreads();
    float4* ob = (float4*)(out + ((size_t)b*Nn + blockIdx.x*128)*Ff);
    if (tid < 96) ob[tid] = ((const float4*)so)[tid];
}

// ---------------- launch ----------------
extern "C" void kernel_launch(void* const* d_in, const int* in_sizes, int n_in,
                              void* d_out, int out_size)
{
    const float* tok   = (const float*)d_in[0];
    const float* Kl    = (const float*)d_in[1];
    const float* Ml    = (const float*)d_in[2];
    const int*   dn    = (const int*)  d_in[3];
    const float* bv    = (const float*)d_in[4];
    const float* u0    = (const float*)d_in[5];
    const float* W_enc = (const float*)d_in[6];
    const float* b_enc = (const float*)d_in[7];
    const float* W_src = (const float*)d_in[8];
    const float* b_src = (const float*)d_in[9];
    const float* W_pou = (const float*)d_in[10];
    const float* Wf1   = (const float*)d_in[11];
    const float* Wz    = (const float*)d_in[12];
    const float* bfv   = (const float*)d_in[13];
    const float* Wf2   = (const float*)d_in[14];
    float* out = (float*)d_out;

    k_encode <<<dim3(Nn/128, Bb),  128>>>(tok, dn, bv, W_enc, b_enc, W_src, b_src, W_pou);
    k_stage1 <<<dim3(4, Bb*Ff, 4),  64>>>(Kl, Ml);
    k_stage2 <<<dim3(Bb*Ff, 2),    384>>>();
    k_solver <<<Bb,             SOLV_T>>>(u0, Wf1, Wf2, Wz, bfv);
    k_ufine  <<<dim3(Nn/128, Bb),  128>>>(out);
}

// round 13
// speedup vs baseline: 1.6575x; 1.6575x over previous
#include <cuda_runtime.h>
#include <math.h>

#define Bb   16
#define Nn   1024
#define DIN  32
#define DZ   64
#define DH   64
#define Ff   3
#define Pp   19
#define PPAD 20
#define NEDGE 171
#define ITERS 50
#define ALPHAc 0.1f
#define INV_SCALE (19.0f/1024.0f)
#define SOLV_T 704

// ---------------- device scratch (static; no allocations) ----------------
__device__ __align__(16) float2 g_wpair[(size_t)Bb*Ff*Nn*PPAD]; // {w,w} pairs for FFMA2 (stage1)
__device__ __align__(16) float  g_wc[(size_t)Bb*Ff*Nn*PPAD];    // compact weights (stage2/ufine)
__device__ __align__(16) float  g_t[(size_t)192*Pp*Nn];         // stage-1 partials
__device__ __align__(16) float  g_khat[2*Bb*Ff*Pp*Pp];          // [mat][b][f][p][q]
__device__ __align__(16) float  g_zpart[Bb*8*DZ];               // per-block z partial sums
__device__ __align__(16) float  g_flpart[Bb*8*64];              // per-block f_latent partials (57 used)
__device__ __align__(16) float  g_uhat[Bb*64];

// packed f32x2 FMA (Blackwell FFMA2)
__device__ __forceinline__ unsigned long long ffma2(unsigned long long a,
                                                    unsigned long long b,
                                                    unsigned long long c) {
    unsigned long long d;
    asm("fma.rn.f32x2 %0, %1, %2, %3;" : "=l"(d) : "l"(a), "l"(b), "l"(c));
    return d;
}
__device__ __forceinline__ float2 ull2f2(unsigned long long v) {
    float2 r;
    asm("mov.b64 {%0,%1}, %2;" : "=f"(r.x), "=f"(r.y) : "l"(v));
    return r;
}
__device__ __forceinline__ unsigned long long packdup(float v) {
    unsigned long long r;
    asm("mov.b64 %0, {%1,%1};" : "=l"(r) : "f"(v));
    return r;
}
__device__ __forceinline__ unsigned long long pack2(float a, float b) {
    unsigned long long r;
    asm("mov.b64 %0, {%1,%2};" : "=l"(r) : "f"(a), "f"(b));
    return r;
}
__device__ __forceinline__ float warp_sum(float v) {
    v += __shfl_xor_sync(0xffffffffu, v, 16);
    v += __shfl_xor_sync(0xffffffffu, v, 8);
    v += __shfl_xor_sync(0xffffffffu, v, 4);
    v += __shfl_xor_sync(0xffffffffu, v, 2);
    v += __shfl_xor_sync(0xffffffffu, v, 1);
    return v;
}

// ---------------- kernel 1: encoder + POU softmax + fused partial reductions ----------------
__global__ __launch_bounds__(128) void k_encode(
    const float* __restrict__ tok, const int* __restrict__ dn,
    const float* __restrict__ bv,
    const float* __restrict__ W_enc, const float* __restrict__ b_enc,
    const float* __restrict__ W_src, const float* __restrict__ b_src,
    const float* __restrict__ W_pou)
{
    __shared__ float sWe[DIN*DZ];
    __shared__ float sWp[DZ*57];
    __shared__ float sWs[DZ*Ff];
    __shared__ float sbe[DZ];
    __shared__ float sbs[Ff];
    __shared__ int   sdn[64];
    __shared__ float sbv[64*Ff];
    __shared__ float sW4[4][DZ];     // warp partials for z-mean
    __shared__ float sFl[4][Pp];     // warp partials for f_latent (per f)

    int b = blockIdx.y;
    int tid = threadIdx.x;
    int wid = tid >> 5, lane = tid & 31;
    for (int i = tid; i < DIN*DZ; i += 128) sWe[i] = W_enc[i];
    for (int i = tid; i < DZ*57;  i += 128) sWp[i] = W_pou[i];
    for (int i = tid; i < DZ*Ff;  i += 128) sWs[i] = W_src[i];
    if (tid < DZ) sbe[tid] = b_enc[tid];
    if (tid < Ff) sbs[tid] = b_src[tid];
    if (tid < 64) sdn[tid] = dn[b*64 + tid];
    for (int i = tid; i < 64*Ff; i += 128) sbv[i] = bv[b*64*Ff + i];
    __syncthreads();

    int n = blockIdx.x*128 + tid;

    float x[DIN];
    const float4* xp = (const float4*)(tok + ((size_t)b*Nn + n)*DIN);
    #pragma unroll
    for (int i = 0; i < DIN/4; i++) {
        float4 v = xp[i];
        x[4*i] = v.x; x[4*i+1] = v.y; x[4*i+2] = v.z; x[4*i+3] = v.w;
    }

    float z[DZ];
    #pragma unroll
    for (int d = 0; d < DZ; d++) z[d] = sbe[d];
    for (int k = 0; k < DIN; k++) {
        float xv = x[k];
        const float* wr = sWe + k*DZ;
        #pragma unroll
        for (int d = 0; d < DZ; d++) z[d] += xv * wr[d];
    }
    #pragma unroll
    for (int d = 0; d < DZ; d++) z[d] = tanhf(z[d]);

    // z-mean partial (deterministic: fixed warp/block reduction order)
    #pragma unroll
    for (int d = 0; d < DZ; d++) {
        float v = warp_sum(z[d]);
        if (lane == 0) sW4[wid][d] = v;
    }
    __syncthreads();
    if (tid < DZ)
        g_zpart[((size_t)b*8 + blockIdx.x)*DZ + tid] =
            sW4[0][tid] + sW4[1][tid] + sW4[2][tid] + sW4[3][tid];

    // f_full
    float ffull[Ff];
    #pragma unroll
    for (int f = 0; f < Ff; f++) {
        float s = sbs[f];
        for (int d = 0; d < DZ; d++) s += z[d]*sWs[d*Ff + f];
        ffull[f] = s;
    }

    // boundary value scatter (last occurrence wins, matching JAX .set)
    float bvv[Ff] = {0.f, 0.f, 0.f};
    for (int k = 0; k < 64; k++) {
        if (sdn[k] == n) {
            bvv[0] = sbv[k*Ff]; bvv[1] = sbv[k*Ff+1]; bvv[2] = sbv[k*Ff+2];
        }
    }

    // softmax over P per field + weight stores + f_latent partials
    for (int f = 0; f < Ff; f++) {
        float lg[Pp];
        #pragma unroll
        for (int p = 0; p < Pp; p++) {
            float s = 0.f;
            for (int d = 0; d < DZ; d++) s += z[d]*sWp[d*57 + p*Ff + f];
            lg[p] = s;
        }
        lg[16] += bvv[f]; lg[17] += bvv[f]; lg[18] += bvv[f];
        float m = lg[0];
        #pragma unroll
        for (int p = 1; p < Pp; p++) m = fmaxf(m, lg[p]);
        float s = 0.f;
        #pragma unroll
        for (int p = 0; p < Pp; p++) { lg[p] = __expf(lg[p]-m); s += lg[p]; }
        float inv = 1.f/s;
        float2* wp = g_wpair + ((size_t)(b*Ff + f)*Nn + n)*PPAD;
        float*  wc = g_wc    + ((size_t)(b*Ff + f)*Nn + n)*PPAD;
        #pragma unroll
        for (int p = 0; p < Pp; p++) {
            float w = lg[p]*inv;
            lg[p] = w;
            wp[p] = make_float2(w, w);
            wc[p] = w;
        }
        // f_latent partial for this field
        __syncthreads();
        #pragma unroll
        for (int p = 0; p < Pp; p++) {
            float v = warp_sum(lg[p]*ffull[f]);
            if (lane == 0) sFl[wid][p] = v;
        }
        __syncthreads();
        if (tid < Pp)
            g_flpart[((size_t)b*8 + blockIdx.x)*64 + tid*Ff + f] =
                sFl[0][tid] + sFl[1][tid] + sFl[2][tid] + sFl[3][tid];
    }
}

// ------------- kernel 2: stage-1 projection  t[p,j] = sum_i W[p,i]*A[i,j] -------------
__global__ __launch_bounds__(64) void k_stage1(const float* __restrict__ Kl,
                                               const float* __restrict__ Ml)
{
    int bf   = blockIdx.y;
    int mat  = blockIdx.z >> 1;
    int half = blockIdx.z & 1;
    int j0   = blockIdx.x*256 + threadIdx.x*4;

    const float* src = (mat ? Ml : Kl) + (size_t)bf*Nn*Nn;
    const unsigned long long* wsrc =
        (const unsigned long long*)(g_wpair + (size_t)bf*Nn*PPAD);

    __shared__ __align__(16) unsigned long long sw[32*PPAD];

    unsigned long long acc[2*Pp];
    #pragma unroll
    for (int i = 0; i < 2*Pp; i++) acc[i] = 0ull;

    for (int ic = 0; ic < 16; ic++) {
        int ib = half*512 + ic*32;
        const unsigned long long* g = wsrc + (size_t)ib*PPAD;
        for (int idx = threadIdx.x; idx < 32*PPAD; idx += 64) sw[idx] = g[idx];
        __syncthreads();
        const float* kptr = src + (size_t)ib*Nn + j0;
        #pragma unroll 4
        for (int ii = 0; ii < 32; ii++) {
            float4 kv = *(const float4*)kptr;
            unsigned long long kx = pack2(kv.x, kv.y);
            unsigned long long ky = pack2(kv.z, kv.w);
            kptr += Nn;
            const unsigned long long* wrow = sw + ii*PPAD;
            #pragma unroll
            for (int p = 0; p < Pp; p++) {
                unsigned long long w = wrow[p];
                acc[2*p]   = ffma2(w, kx, acc[2*p]);
                acc[2*p+1] = ffma2(w, ky, acc[2*p+1]);
            }
        }
        __syncthreads();
    }

    float* tp = g_t + ((size_t)((bf*2 + mat)*2 + half))*Pp*Nn;
    #pragma unroll
    for (int p = 0; p < Pp; p++) {
        float2 a0 = ull2f2(acc[2*p]);
        float2 a1 = ull2f2(acc[2*p+1]);
        *(float4*)(tp + p*Nn + j0) = make_float4(a0.x, a0.y, a1.x, a1.y);
    }
}

// ------------- stage-2: K_hat[p,q] = (t W^T)/scale + Dirichlet rows -------------
__global__ __launch_bounds__(384) void k_stage2()
{
    int bf = blockIdx.x;
    int mat = blockIdx.y;
    __shared__ float tS[Pp][129];
    __shared__ float wS[128*PPAD];
    int t = threadIdx.x;
    int p = t % Pp, q = t / Pp;
    bool act = (t < Pp*Pp);
    float acc = 0.f;
    const float* t0 = g_t + (size_t)((bf*2 + mat)*2)*Pp*Nn;
    const float* t1 = t0 + Pp*Nn;
    const float* wsrc0 = g_wc + (size_t)bf*Nn*PPAD;
    for (int jc = 0; jc < 8; jc++) {
        for (int idx = t; idx < Pp*128; idx += 384) {
            int pp = idx >> 7, jj = idx & 127;
            tS[pp][jj] = t0[pp*Nn + jc*128 + jj] + t1[pp*Nn + jc*128 + jj];
        }
        const float* wsrc = wsrc0 + (size_t)jc*128*PPAD;
        for (int idx = t; idx < 128*PPAD; idx += 384) wS[idx] = wsrc[idx];
        __syncthreads();
        if (act) {
            #pragma unroll 8
            for (int jj = 0; jj < 128; jj++) acc += tS[p][jj]*wS[jj*PPAD + q];
        }
        __syncthreads();
    }
    if (act) {
        float v = acc * INV_SCALE;
        if (p >= Pp-3) v = (p == q) ? 1.f : 0.f;
        g_khat[((size_t)mat*Bb*Ff + bf)*Pp*Pp + p*Pp + q] = v;
    }
}

// ------------- solver: prologue reductions + 50 damped fixed-point iterations -------------
// 704 threads: flux thread t = edge*4 + qt; qt handles 8 h-pairs (16 h) as
// packed f32x2 (FFMA2). Weight slices padded so the 4 qt slices start in
// different bank groups (stride 66/34 ull -> byte offsets 528/272 -> banks
// 0/4/8/12): all weight LDS are single-phase broadcasts.
__global__ __launch_bounds__(SOLV_T) void k_solver(const float* __restrict__ u_init,
                                                   const float* __restrict__ Wf1,
                                                   const float* __restrict__ Wf2,
                                                   const float* __restrict__ Wz,
                                                   const float* __restrict__ bfv)
{
    int b = blockIdx.x, t = threadIdx.x;
    __shared__ float Ks[Ff*Pp*Pp];
    __shared__ __align__(16) unsigned long long w1s[4*66]; // per qt: 8 hp x 8 ull (A0..A5,zp,pad), +2 pad
    __shared__ __align__(16) unsigned long long w2s[4*34]; // per qt: 8 hp x 4 ull (C0..C2,pad), +2 pad
    __shared__ float srcs[64];
    __shared__ float flux[NEDGE*4];
    __shared__ float ua[64], ub[64];
    __shared__ float mz[DZ];
    __shared__ float sfl[64];

    for (int i = t; i < Ff*Pp*Pp; i += SOLV_T)
        Ks[i] = g_khat[(size_t)b*Ff*Pp*Pp + i];
    if (t < DH) {  // scatter Wf1/Wf2 into padded per-qt h-pair slices
        int h = t, hpg = h >> 1, par = h & 1;
        int qts = hpg >> 3, hpl = hpg & 7;
        float* w1f = (float*)w1s;
        float* w2f = (float*)w2s;
        int b1 = (qts*66 + hpl*8)*2 + par;
        w1f[b1 + 0]  = Wf1[0*DH + h];
        w1f[b1 + 2]  = Wf1[1*DH + h];
        w1f[b1 + 4]  = Wf1[2*DH + h];
        w1f[b1 + 6]  = Wf1[3*DH + h];
        w1f[b1 + 8]  = Wf1[4*DH + h];
        w1f[b1 + 10] = Wf1[5*DH + h];
        w1f[b1 + 14] = 0.f;
        int b2 = (qts*34 + hpl*4)*2 + par;
        w2f[b2 + 0] = Wf2[h*Ff + 0];
        w2f[b2 + 2] = Wf2[h*Ff + 1];
        w2f[b2 + 4] = Wf2[h*Ff + 2];
        w2f[b2 + 6] = 0.f;
    }
    if (t < Pp*Ff) ua[t] = u_init[b*Pp*Ff + t];
    // reduce z-mean and f_latent partials (deterministic fixed order)
    if (t < DZ) {
        float s = 0.f;
        #pragma unroll
        for (int k = 0; k < 8; k++) s += g_zpart[((size_t)b*8 + k)*DZ + t];
        mz[t] = s * (1.f/Nn);
    } else if (t >= 64 && t < 64 + Pp*Ff) {
        int k = t - 64;
        float s = 0.f;
        #pragma unroll
        for (int j = 0; j < 8; j++) s += g_flpart[((size_t)b*8 + j)*64 + k];
        sfl[k] = s * INV_SCALE;
    }
    __syncthreads();

    if (t < DH) {  // zp = mean(z) @ Wz + bf  -> slot 6 of the h-pair record
        float a = bfv[t];
        #pragma unroll 8
        for (int d = 0; d < DZ; d++) a += mz[d]*Wz[d*DH + t];
        int h = t, hpg = h >> 1, par = h & 1;
        int qts = hpg >> 3, hpl = hpg & 7;
        ((float*)w1s)[(qts*66 + hpl*8)*2 + 12 + par] = a;
    } else if (t >= 64 && t < 64 + Pp*Ff) {  // src_term = M_hat @ f_latent
        int k = t - 64;
        int p = k / Ff, f = k % Ff;
        const float* mrow = g_khat + ((size_t)Bb*Ff + b*Ff + f)*Pp*Pp + p*Pp;
        float s = 0.f;
        #pragma unroll
        for (int q = 0; q < Pp; q++) s += mrow[q]*sfl[q*Ff + f];
        srcs[k] = s;
    }

    // flux-thread mapping: keep ALL warps converged (clamp e, guard the write)
    int e_raw = t >> 2;
    int qt = t & 3;
    int e = (e_raw < NEDGE) ? e_raw : 0;
    int ei, ej;
    {
        int ee = e, a = 0;
        while (ee >= Pp-1-a) { ee -= (Pp-1-a); a++; }
        ei = a; ej = a + 1 + ee;
    }
    const unsigned long long* w1u = w1s + qt*66;
    const unsigned long long* w2u = w2s + qt*34;
    __syncthreads();

    float* cur = ua; float* nxt = ub;
    for (int it = 0; it < ITERS; it++) {
        {
            unsigned long long up0 = packdup(cur[ei*Ff+0]);
            unsigned long long up1 = packdup(cur[ei*Ff+1]);
            unsigned long long up2 = packdup(cur[ei*Ff+2]);
            unsigned long long up3 = packdup(cur[ej*Ff+0]);
            unsigned long long up4 = packdup(cur[ej*Ff+1]);
            unsigned long long up5 = packdup(cur[ej*Ff+2]);
            unsigned long long acc0 = 0ull, acc1 = 0ull, acc2 = 0ull;
            #pragma unroll
            for (int hp = 0; hp < 8; hp++) {
                const unsigned long long* r1 = w1u + hp*8;
                ulonglong2 a01 = *(const ulonglong2*)(r1);
                ulonglong2 a23 = *(const ulonglong2*)(r1 + 2);
                ulonglong2 a45 = *(const ulonglong2*)(r1 + 4);
                unsigned long long s = r1[6];            // zp pair
                s = ffma2(up0, a01.x, s);
                s = ffma2(up1, a01.y, s);
                s = ffma2(up2, a23.x, s);
                s = ffma2(up3, a23.y, s);
                s = ffma2(up4, a45.x, s);
                s = ffma2(up5, a45.y, s);
                float2 sv = ull2f2(s);
                float r0, r1f;
                asm("tanh.approx.f32 %0, %1;" : "=f"(r0)  : "f"(sv.x));
                asm("tanh.approx.f32 %0, %1;" : "=f"(r1f) : "f"(sv.y));
                unsigned long long rp = pack2(r0, r1f);
                const unsigned long long* r2 = w2u + hp*4;
                ulonglong2 c01 = *(const ulonglong2*)(r2);
                unsigned long long c2 = r2[2];
                acc0 = ffma2(rp, c01.x, acc0);
                acc1 = ffma2(rp, c01.y, acc1);
                acc2 = ffma2(rp, c2,    acc2);
            }
            float2 f0 = ull2f2(acc0), f1 = ull2f2(acc1), f2 = ull2f2(acc2);
            float a0 = f0.x + f0.y, a1 = f1.x + f1.y, a2 = f2.x + f2.y;
            // reduce across the 4 quarter-threads (nibble-aligned lanes)
            a0 += __shfl_xor_sync(0xffffffffu, a0, 1);
            a0 += __shfl_xor_sync(0xffffffffu, a0, 2);
            a1 += __shfl_xor_sync(0xffffffffu, a1, 1);
            a1 += __shfl_xor_sync(0xffffffffu, a1, 2);
            a2 += __shfl_xor_sync(0xffffffffu, a2, 1);
            a2 += __shfl_xor_sync(0xffffffffu, a2, 2);
            if (qt == 0 && e_raw < NEDGE) {
                flux[e*4+0] = a0; flux[e*4+1] = a1; flux[e*4+2] = a2;
            }
        }
        __syncthreads();
        if (t < Pp*Ff) {
            int p = t / Ff, f = t % Ff;
            const float* kr = Ks + f*Pp*Pp + p*Pp;
            float diff = 0.f;
            #pragma unroll
            for (int q = 0; q < Pp; q++) diff += kr[q]*cur[q*Ff + f];
            float ft = 0.f;
            for (int q = 0; q < p; q++) {           // p == ej -> +flux
                int ee = q*(Pp-1) - (q*(q-1))/2 + (p - q - 1);
                ft += flux[ee*4 + f];
            }
            for (int q = p+1; q < Pp; q++) {        // p == ei -> -flux
                int ee = p*(Pp-1) - (p*(p-1))/2 + (q - p - 1);
                ft -= flux[ee*4 + f];
            }
            float r = diff - srcs[t] - ft;
            if (p >= Pp-3) r = cur[t] - ((p == Pp-3) ? 1.f : 0.f);
            nxt[t] = cur[t] - ALPHAc*r;
        }
        __syncthreads();
        float* tmp = cur; cur = nxt; nxt = tmp;
    }
    if (t < Pp*Ff) g_uhat[b*64 + t] = cur[t];
}

// ------------- u_fine = W^T u_coarse (compact weights, vectorized) -------------
__global__ __launch_bounds__(128) void k_ufine(float* __restrict__ out)
{
    int b = blockIdx.y;
    int tid = threadIdx.x;
    int n = blockIdx.x*128 + tid;
    __shared__ float us[64];
    __shared__ __align__(16) float so[384];
    if (tid < 64) us[tid] = g_uhat[b*64 + tid];
    __syncthreads();
    float o[Ff];
    #pragma unroll
    for (int f = 0; f < Ff; f++) {
        const float4* wv = (const float4*)(g_wc + ((size_t)(b*Ff + f)*Nn + n)*PPAD);
        float acc = 0.f;
        #pragma unroll
        for (int k = 0; k < 5; k++) {
            float4 w4 = wv[k];
            int p0 = 4*k;
            acc += w4.x*us[p0*Ff + f];
            if (p0+1 < Pp) acc += w4.y*us[(p0+1)*Ff + f];
            if (p0+2 < Pp) acc += w4.z*us[(p0+2)*Ff + f];
            if (p0+3 < Pp) acc += w4.w*us[(p0+3)*Ff + f];
        }
        o[f] = acc;
    }
    so[tid*3+0] = o[0]; so[tid*3+1] = o[1]; so[tid*3+2] = o[2];
    __syncthreads();
    float4* ob = (float4*)(out + ((size_t)b*Nn + blockIdx.x*128)*Ff);
    if (tid < 96) ob[tid] = ((const float4*)so)[tid];
}

// ---------------- launch ----------------
extern "C" void kernel_launch(void* const* d_in, const int* in_sizes, int n_in,
                              void* d_out, int out_size)
{
    const float* tok   = (const float*)d_in[0];
    const float* Kl    = (const float*)d_in[1];
    const float* Ml    = (const float*)d_in[2];
    const int*   dn    = (const int*)  d_in[3];
    const float* bv    = (const float*)d_in[4];
    const float* u0    = (const float*)d_in[5];
    const float* W_enc = (const float*)d_in[6];
    const float* b_enc = (const float*)d_in[7];
    const float* W_src = (const float*)d_in[8];
    const float* b_src = (const float*)d_in[9];
    const float* W_pou = (const float*)d_in[10];
    const float* Wf1   = (const float*)d_in[11];
    const float* Wz    = (const float*)d_in[12];
    const float* bfv   = (const float*)d_in[13];
    const float* Wf2   = (const float*)d_in[14];
    float* out = (float*)d_out;

    k_encode <<<dim3(Nn/128, Bb),  128>>>(tok, dn, bv, W_enc, b_enc, W_src, b_src, W_pou);
    k_stage1 <<<dim3(4, Bb*Ff, 4),  64>>>(Kl, Ml);
    k_stage2 <<<dim3(Bb*Ff, 2),    384>>>();
    k_solver <<<Bb,             SOLV_T>>>(u0, Wf1, Wf2, Wz, bfv);
    k_ufine  <<<dim3(Nn/128, Bb),  128>>>(out);
}

// round 14
// speedup vs baseline: 1.8466x; 1.1141x over previous
#include <cuda_runtime.h>
#include <math.h>

#define Bb   16
#define Nn   1024
#define DIN  32
#define DZ   64
#define DH   64
#define Ff   3
#define Pp   19
#define PPAD 20
#define NEDGE 171
#define ITERS 50
#define ALPHAc 0.1f
#define INV_SCALE (19.0f/1024.0f)
#define SOLV_T 704

// ---------------- device scratch (static; no allocations) ----------------
__device__ __align__(16) float2 g_wpair[(size_t)Bb*Ff*Nn*PPAD]; // {w,w} pairs for FFMA2 (stage1)
__device__ __align__(16) float  g_wc[(size_t)Bb*Ff*Nn*PPAD];    // compact weights (stage2/ufine)
__device__ __align__(16) float  g_t[(size_t)192*Pp*Nn];         // stage-1 partials
__device__ __align__(16) float  g_khat[2*Bb*Ff*Pp*Pp];          // [mat][b][f][p][q]
__device__ __align__(16) float  g_zpart[Bb*8*DZ];               // per-block z partial sums
__device__ __align__(16) float  g_flpart[Bb*8*64];              // per-block f_latent partials (57 used)
__device__ __align__(16) float  g_uhat[Bb*64];

// packed f32x2 FMA (Blackwell FFMA2)
__device__ __forceinline__ unsigned long long ffma2(unsigned long long a,
                                                    unsigned long long b,
                                                    unsigned long long c) {
    unsigned long long d;
    asm("fma.rn.f32x2 %0, %1, %2, %3;" : "=l"(d) : "l"(a), "l"(b), "l"(c));
    return d;
}
__device__ __forceinline__ float2 ull2f2(unsigned long long v) {
    float2 r;
    asm("mov.b64 {%0,%1}, %2;" : "=f"(r.x), "=f"(r.y) : "l"(v));
    return r;
}
__device__ __forceinline__ unsigned long long packdup(float v) {
    unsigned long long r;
    asm("mov.b64 %0, {%1,%1};" : "=l"(r) : "f"(v));
    return r;
}
__device__ __forceinline__ unsigned long long pack2(float a, float b) {
    unsigned long long r;
    asm("mov.b64 %0, {%1,%2};" : "=l"(r) : "f"(a), "f"(b));
    return r;
}
__device__ __forceinline__ float warp_sum(float v) {
    v += __shfl_xor_sync(0xffffffffu, v, 16);
    v += __shfl_xor_sync(0xffffffffu, v, 8);
    v += __shfl_xor_sync(0xffffffffu, v, 4);
    v += __shfl_xor_sync(0xffffffffu, v, 2);
    v += __shfl_xor_sync(0xffffffffu, v, 1);
    return v;
}

// ---------------- kernel 1: encoder + POU softmax + fused partial reductions ----------------
__global__ __launch_bounds__(128) void k_encode(
    const float* __restrict__ tok, const int* __restrict__ dn,
    const float* __restrict__ bv,
    const float* __restrict__ W_enc, const float* __restrict__ b_enc,
    const float* __restrict__ W_src, const float* __restrict__ b_src,
    const float* __restrict__ W_pou)
{
    __shared__ float sWe[DIN*DZ];
    __shared__ float sWp[DZ*57];
    __shared__ float sWs[DZ*Ff];
    __shared__ float sbe[DZ];
    __shared__ float sbs[Ff];
    __shared__ int   sdn[64];
    __shared__ float sbv[64*Ff];
    __shared__ float sW4[4][DZ];     // warp partials for z-mean
    __shared__ float sFl[4][Pp];     // warp partials for f_latent (per f)

    int b = blockIdx.y;
    int tid = threadIdx.x;
    int wid = tid >> 5, lane = tid & 31;
    for (int i = tid; i < DIN*DZ; i += 128) sWe[i] = W_enc[i];
    for (int i = tid; i < DZ*57;  i += 128) sWp[i] = W_pou[i];
    for (int i = tid; i < DZ*Ff;  i += 128) sWs[i] = W_src[i];
    if (tid < DZ) sbe[tid] = b_enc[tid];
    if (tid < Ff) sbs[tid] = b_src[tid];
    if (tid < 64) sdn[tid] = dn[b*64 + tid];
    for (int i = tid; i < 64*Ff; i += 128) sbv[i] = bv[b*64*Ff + i];
    __syncthreads();

    int n = blockIdx.x*128 + tid;

    float x[DIN];
    const float4* xp = (const float4*)(tok + ((size_t)b*Nn + n)*DIN);
    #pragma unroll
    for (int i = 0; i < DIN/4; i++) {
        float4 v = xp[i];
        x[4*i] = v.x; x[4*i+1] = v.y; x[4*i+2] = v.z; x[4*i+3] = v.w;
    }

    float z[DZ];
    #pragma unroll
    for (int d = 0; d < DZ; d++) z[d] = sbe[d];
    for (int k = 0; k < DIN; k++) {
        float xv = x[k];
        const float* wr = sWe + k*DZ;
        #pragma unroll
        for (int d = 0; d < DZ; d++) z[d] += xv * wr[d];
    }
    #pragma unroll
    for (int d = 0; d < DZ; d++) z[d] = tanhf(z[d]);

    // z-mean partial (deterministic: fixed warp/block reduction order)
    #pragma unroll
    for (int d = 0; d < DZ; d++) {
        float v = warp_sum(z[d]);
        if (lane == 0) sW4[wid][d] = v;
    }
    __syncthreads();
    if (tid < DZ)
        g_zpart[((size_t)b*8 + blockIdx.x)*DZ + tid] =
            sW4[0][tid] + sW4[1][tid] + sW4[2][tid] + sW4[3][tid];

    // f_full
    float ffull[Ff];
    #pragma unroll
    for (int f = 0; f < Ff; f++) {
        float s = sbs[f];
        for (int d = 0; d < DZ; d++) s += z[d]*sWs[d*Ff + f];
        ffull[f] = s;
    }

    // boundary value scatter (last occurrence wins, matching JAX .set)
    float bvv[Ff] = {0.f, 0.f, 0.f};
    for (int k = 0; k < 64; k++) {
        if (sdn[k] == n) {
            bvv[0] = sbv[k*Ff]; bvv[1] = sbv[k*Ff+1]; bvv[2] = sbv[k*Ff+2];
        }
    }

    // softmax over P per field + weight stores + f_latent partials
    for (int f = 0; f < Ff; f++) {
        float lg[Pp];
        #pragma unroll
        for (int p = 0; p < Pp; p++) {
            float s = 0.f;
            for (int d = 0; d < DZ; d++) s += z[d]*sWp[d*57 + p*Ff + f];
            lg[p] = s;
        }
        lg[16] += bvv[f]; lg[17] += bvv[f]; lg[18] += bvv[f];
        float m = lg[0];
        #pragma unroll
        for (int p = 1; p < Pp; p++) m = fmaxf(m, lg[p]);
        float s = 0.f;
        #pragma unroll
        for (int p = 0; p < Pp; p++) { lg[p] = __expf(lg[p]-m); s += lg[p]; }
        float inv = 1.f/s;
        float2* wp = g_wpair + ((size_t)(b*Ff + f)*Nn + n)*PPAD;
        float*  wc = g_wc    + ((size_t)(b*Ff + f)*Nn + n)*PPAD;
        #pragma unroll
        for (int p = 0; p < Pp; p++) {
            float w = lg[p]*inv;
            lg[p] = w;
            wp[p] = make_float2(w, w);
            wc[p] = w;
        }
        // f_latent partial for this field
        __syncthreads();
        #pragma unroll
        for (int p = 0; p < Pp; p++) {
            float v = warp_sum(lg[p]*ffull[f]);
            if (lane == 0) sFl[wid][p] = v;
        }
        __syncthreads();
        if (tid < Pp)
            g_flpart[((size_t)b*8 + blockIdx.x)*64 + tid*Ff + f] =
                sFl[0][tid] + sFl[1][tid] + sFl[2][tid] + sFl[3][tid];
    }
}

// ------------- kernel 2: stage-1 projection  t[p,j] = sum_i W[p,i]*A[i,j] -------------
__global__ __launch_bounds__(64) void k_stage1(const float* __restrict__ Kl,
                                               const float* __restrict__ Ml)
{
    int bf   = blockIdx.y;
    int mat  = blockIdx.z >> 1;
    int half = blockIdx.z & 1;
    int j0   = blockIdx.x*256 + threadIdx.x*4;

    const float* src = (mat ? Ml : Kl) + (size_t)bf*Nn*Nn;
    const unsigned long long* wsrc =
        (const unsigned long long*)(g_wpair + (size_t)bf*Nn*PPAD);

    __shared__ __align__(16) unsigned long long sw[32*PPAD];

    unsigned long long acc[2*Pp];
    #pragma unroll
    for (int i = 0; i < 2*Pp; i++) acc[i] = 0ull;

    for (int ic = 0; ic < 16; ic++) {
        int ib = half*512 + ic*32;
        const unsigned long long* g = wsrc + (size_t)ib*PPAD;
        for (int idx = threadIdx.x; idx < 32*PPAD; idx += 64) sw[idx] = g[idx];
        __syncthreads();
        const float* kptr = src + (size_t)ib*Nn + j0;
        #pragma unroll 4
        for (int ii = 0; ii < 32; ii++) {
            float4 kv = *(const float4*)kptr;
            unsigned long long kx = pack2(kv.x, kv.y);
            unsigned long long ky = pack2(kv.z, kv.w);
            kptr += Nn;
            const unsigned long long* wrow = sw + ii*PPAD;
            #pragma unroll
            for (int p = 0; p < Pp; p++) {
                unsigned long long w = wrow[p];
                acc[2*p]   = ffma2(w, kx, acc[2*p]);
                acc[2*p+1] = ffma2(w, ky, acc[2*p+1]);
            }
        }
        __syncthreads();
    }

    float* tp = g_t + ((size_t)((bf*2 + mat)*2 + half))*Pp*Nn;
    #pragma unroll
    for (int p = 0; p < Pp; p++) {
        float2 a0 = ull2f2(acc[2*p]);
        float2 a1 = ull2f2(acc[2*p+1]);
        *(float4*)(tp + p*Nn + j0) = make_float4(a0.x, a0.y, a1.x, a1.y);
    }
}

// ------------- stage-2: K_hat[p,q] = (t W^T)/scale + Dirichlet rows -------------
__global__ __launch_bounds__(384) void k_stage2()
{
    int bf = blockIdx.x;
    int mat = blockIdx.y;
    __shared__ float tS[Pp][129];
    __shared__ float wS[128*PPAD];
    int t = threadIdx.x;
    int p = t % Pp, q = t / Pp;
    bool act = (t < Pp*Pp);
    float acc = 0.f;
    const float* t0 = g_t + (size_t)((bf*2 + mat)*2)*Pp*Nn;
    const float* t1 = t0 + Pp*Nn;
    const float* wsrc0 = g_wc + (size_t)bf*Nn*PPAD;
    for (int jc = 0; jc < 8; jc++) {
        for (int idx = t; idx < Pp*128; idx += 384) {
            int pp = idx >> 7, jj = idx & 127;
            tS[pp][jj] = t0[pp*Nn + jc*128 + jj] + t1[pp*Nn + jc*128 + jj];
        }
        const float* wsrc = wsrc0 + (size_t)jc*128*PPAD;
        for (int idx = t; idx < 128*PPAD; idx += 384) wS[idx] = wsrc[idx];
        __syncthreads();
        if (act) {
            #pragma unroll 8
            for (int jj = 0; jj < 128; jj++) acc += tS[p][jj]*wS[jj*PPAD + q];
        }
        __syncthreads();
    }
    if (act) {
        float v = acc * INV_SCALE;
        if (p >= Pp-3) v = (p == q) ? 1.f : 0.f;
        g_khat[((size_t)mat*Bb*Ff + bf)*Pp*Pp + p*Pp + q] = v;
    }
}

// ------------- solver: prologue reductions + 50 damped fixed-point iterations -------------
// 704 threads. Flux: t = edge*4 + qt, each qt handles 8 h-pairs (FFMA2),
// weight slices bank-padded (66/34 ull) + c01 register-cached.
// Residual update: 4-way split over t<256 (k = t>>2 clamped, sub = t&3),
// partials combined with nibble shfl (all participating warps fully converged).
__global__ __launch_bounds__(SOLV_T, 1) void k_solver(const float* __restrict__ u_init,
                                                      const float* __restrict__ Wf1,
                                                      const float* __restrict__ Wf2,
                                                      const float* __restrict__ Wz,
                                                      const float* __restrict__ bfv)
{
    int b = blockIdx.x, t = threadIdx.x;
    __shared__ float Ks[Ff*Pp*Pp];
    __shared__ __align__(16) unsigned long long w1s[4*66]; // per qt: 8 hp x 8 ull (A0..A5,zp,pad), +2 pad
    __shared__ __align__(16) unsigned long long w2s[4*34]; // per qt: 8 hp x 4 ull (C0..C2,pad), +2 pad
    __shared__ float srcs[64];
    __shared__ float flux[NEDGE*4];
    __shared__ float ua[64], ub[64];
    __shared__ float mz[DZ];
    __shared__ float sfl[64];

    for (int i = t; i < Ff*Pp*Pp; i += SOLV_T)
        Ks[i] = g_khat[(size_t)b*Ff*Pp*Pp + i];
    if (t < DH) {  // scatter Wf1/Wf2 into padded per-qt h-pair slices
        int h = t, hpg = h >> 1, par = h & 1;
        int qts = hpg >> 3, hpl = hpg & 7;
        float* w1f = (float*)w1s;
        float* w2f = (float*)w2s;
        int b1 = (qts*66 + hpl*8)*2 + par;
        w1f[b1 + 0]  = Wf1[0*DH + h];
        w1f[b1 + 2]  = Wf1[1*DH + h];
        w1f[b1 + 4]  = Wf1[2*DH + h];
        w1f[b1 + 6]  = Wf1[3*DH + h];
        w1f[b1 + 8]  = Wf1[4*DH + h];
        w1f[b1 + 10] = Wf1[5*DH + h];
        w1f[b1 + 14] = 0.f;
        int b2 = (qts*34 + hpl*4)*2 + par;
        w2f[b2 + 0] = Wf2[h*Ff + 0];
        w2f[b2 + 2] = Wf2[h*Ff + 1];
        w2f[b2 + 4] = Wf2[h*Ff + 2];
        w2f[b2 + 6] = 0.f;
    }
    if (t < Pp*Ff) ua[t] = u_init[b*Pp*Ff + t];
    // reduce z-mean and f_latent partials (deterministic fixed order)
    if (t < DZ) {
        float s = 0.f;
        #pragma unroll
        for (int k = 0; k < 8; k++) s += g_zpart[((size_t)b*8 + k)*DZ + t];
        mz[t] = s * (1.f/Nn);
    } else if (t >= 64 && t < 64 + Pp*Ff) {
        int k = t - 64;
        float s = 0.f;
        #pragma unroll
        for (int j = 0; j < 8; j++) s += g_flpart[((size_t)b*8 + j)*64 + k];
        sfl[k] = s * INV_SCALE;
    }
    __syncthreads();

    if (t < DH) {  // zp = mean(z) @ Wz + bf  -> slot 6 of the h-pair record
        float a = bfv[t];
        #pragma unroll 8
        for (int d = 0; d < DZ; d++) a += mz[d]*Wz[d*DH + t];
        int h = t, hpg = h >> 1, par = h & 1;
        int qts = hpg >> 3, hpl = hpg & 7;
        ((float*)w1s)[(qts*66 + hpl*8)*2 + 12 + par] = a;
    } else if (t >= 64 && t < 64 + Pp*Ff) {  // src_term = M_hat @ f_latent
        int k = t - 64;
        int p = k / Ff, f = k % Ff;
        const float* mrow = g_khat + ((size_t)Bb*Ff + b*Ff + f)*Pp*Pp + p*Pp;
        float s = 0.f;
        #pragma unroll
        for (int q = 0; q < Pp; q++) s += mrow[q]*sfl[q*Ff + f];
        srcs[k] = s;
    }

    // flux-thread mapping: keep ALL warps converged (clamp e, guard the write)
    int e_raw = t >> 2;
    int qt = t & 3;
    int e = (e_raw < NEDGE) ? e_raw : 0;
    int ei, ej;
    {
        int ee = e, a = 0;
        while (ee >= Pp-1-a) { ee -= (Pp-1-a); a++; }
        ei = a; ej = a + 1 + ee;
    }
    const unsigned long long* w1u = w1s + qt*66;
    const unsigned long long* w2u = w2s + qt*34;

    // residual-update mapping (4-way split, clamped so warps 0-7 stay converged)
    int k2 = t >> 2; if (k2 > 56) k2 = 56;
    int sub = t & 3;
    int p2 = k2 / Ff, f2 = k2 % Ff;
    __syncthreads();

    // register-cache the c01 weight pairs (loop-invariant; LDS can't be
    // hoisted across the barrier by ptxas)
    ulonglong2 c01r[8];
    #pragma unroll
    for (int hp = 0; hp < 8; hp++) c01r[hp] = *(const ulonglong2*)(w2u + hp*4);

    float* cur = ua; float* nxt = ub;
    for (int it = 0; it < ITERS; it++) {
        {
            unsigned long long up0 = packdup(cur[ei*Ff+0]);
            unsigned long long up1 = packdup(cur[ei*Ff+1]);
            unsigned long long up2 = packdup(cur[ei*Ff+2]);
            unsigned long long up3 = packdup(cur[ej*Ff+0]);
            unsigned long long up4 = packdup(cur[ej*Ff+1]);
            unsigned long long up5 = packdup(cur[ej*Ff+2]);
            unsigned long long acc0 = 0ull, acc1 = 0ull, acc2 = 0ull;
            #pragma unroll
            for (int hp = 0; hp < 8; hp++) {
                const unsigned long long* r1 = w1u + hp*8;
                ulonglong2 a01 = *(const ulonglong2*)(r1);
                ulonglong2 a23 = *(const ulonglong2*)(r1 + 2);
                ulonglong2 a45 = *(const ulonglong2*)(r1 + 4);
                unsigned long long s = r1[6];            // zp pair
                s = ffma2(up0, a01.x, s);
                s = ffma2(up1, a01.y, s);
                s = ffma2(up2, a23.x, s);
                s = ffma2(up3, a23.y, s);
                s = ffma2(up4, a45.x, s);
                s = ffma2(up5, a45.y, s);
                float2 sv = ull2f2(s);
                float r0, r1f;
                asm("tanh.approx.f32 %0, %1;" : "=f"(r0)  : "f"(sv.x));
                asm("tanh.approx.f32 %0, %1;" : "=f"(r1f) : "f"(sv.y));
                unsigned long long rp = pack2(r0, r1f);
                unsigned long long c2 = w2u[hp*4 + 2];
                acc0 = ffma2(rp, c01r[hp].x, acc0);
                acc1 = ffma2(rp, c01r[hp].y, acc1);
                acc2 = ffma2(rp, c2,         acc2);
            }
            float2 f0 = ull2f2(acc0), f1 = ull2f2(acc1), f2v = ull2f2(acc2);
            float a0 = f0.x + f0.y, a1 = f1.x + f1.y, a2 = f2v.x + f2v.y;
            // reduce across the 4 quarter-threads (nibble-aligned lanes)
            a0 += __shfl_xor_sync(0xffffffffu, a0, 1);
            a0 += __shfl_xor_sync(0xffffffffu, a0, 2);
            a1 += __shfl_xor_sync(0xffffffffu, a1, 1);
            a1 += __shfl_xor_sync(0xffffffffu, a1, 2);
            a2 += __shfl_xor_sync(0xffffffffu, a2, 1);
            a2 += __shfl_xor_sync(0xffffffffu, a2, 2);
            if (qt == 0 && e_raw < NEDGE) {
                flux[e*4+0] = a0; flux[e*4+1] = a1; flux[e*4+2] = a2;
            }
        }
        __syncthreads();
        if (t < 256) {   // 4-way split residual update; warps 0-7 fully converged
            const float* kr = Ks + f2*Pp*Pp + p2*Pp;
            float part = 0.f;
            #pragma unroll
            for (int q = sub; q < Pp; q += 4) part += kr[q]*cur[q*Ff + f2];
            #pragma unroll
            for (int idx = sub; idx < Pp-1; idx += 4) {
                int q = idx + (idx >= p2 ? 1 : 0);
                if (q < p2) {
                    int ee = q*(Pp-1) - (q*(q-1))/2 + (p2 - q - 1);
                    part -= flux[ee*4 + f2];   // +flux in ft -> -ft in r
                } else {
                    int ee = p2*(Pp-1) - (p2*(p2-1))/2 + (q - p2 - 1);
                    part += flux[ee*4 + f2];
                }
            }
            // NOTE sign: part = diff_partial - flux_term_partial
            part += __shfl_xor_sync(0xffffffffu, part, 1);
            part += __shfl_xor_sync(0xffffffffu, part, 2);
            if (sub == 0) {
                float r = part - srcs[k2];
                if (p2 >= Pp-3) r = cur[k2] - ((p2 == Pp-3) ? 1.f : 0.f);
                nxt[k2] = cur[k2] - ALPHAc*r;
            }
        }
        __syncthreads();
        float* tmp = cur; cur = nxt; nxt = tmp;
    }
    if (t < Pp*Ff) g_uhat[b*64 + t] = cur[t];
}

// ------------- u_fine = W^T u_coarse (compact weights, vectorized) -------------
__global__ __launch_bounds__(128) void k_ufine(float* __restrict__ out)
{
    int b = blockIdx.y;
    int tid = threadIdx.x;
    int n = blockIdx.x*128 + tid;
    __shared__ float us[64];
    __shared__ __align__(16) float so[384];
    if (tid < 64) us[tid] = g_uhat[b*64 + tid];
    __syncthreads();
    float o[Ff];
    #pragma unroll
    for (int f = 0; f < Ff; f++) {
        const float4* wv = (const float4*)(g_wc + ((size_t)(b*Ff + f)*Nn + n)*PPAD);
        float acc = 0.f;
        #pragma unroll
        for (int k = 0; k < 5; k++) {
            float4 w4 = wv[k];
            int p0 = 4*k;
            acc += w4.x*us[p0*Ff + f];
            if (p0+1 < Pp) acc += w4.y*us[(p0+1)*Ff + f];
            if (p0+2 < Pp) acc += w4.z*us[(p0+2)*Ff + f];
            if (p0+3 < Pp) acc += w4.w*us[(p0+3)*Ff + f];
        }
        o[f] = acc;
    }
    so[tid*3+0] = o[0]; so[tid*3+1] = o[1]; so[tid*3+2] = o[2];
    __syncthreads();
    float4* ob = (float4*)(out + ((size_t)b*Nn + blockIdx.x*128)*Ff);
    if (tid < 96) ob[tid] = ((const float4*)so)[tid];
}

// ---------------- launch ----------------
extern "C" void kernel_launch(void* const* d_in, const int* in_sizes, int n_in,
                              void* d_out, int out_size)
{
    const float* tok   = (const float*)d_in[0];
    const float* Kl    = (const float*)d_in[1];
    const float* Ml    = (const float*)d_in[2];
    const int*   dn    = (const int*)  d_in[3];
    const float* bv    = (const float*)d_in[4];
    const float* u0    = (const float*)d_in[5];
    const float* W_enc = (const float*)d_in[6];
    const float* b_enc = (const float*)d_in[7];
    const float* W_src = (const float*)d_in[8];
    const float* b_src = (const float*)d_in[9];
    const float* W_pou = (const float*)d_in[10];
    const float* Wf1   = (const float*)d_in[11];
    const float* Wz    = (const float*)d_in[12];
    const float* bfv   = (const float*)d_in[13];
    const float* Wf2   = (const float*)d_in[14];
    float* out = (float*)d_out;

    k_encode <<<dim3(Nn/128, Bb),  128>>>(tok, dn, bv, W_enc, b_enc, W_src, b_src, W_pou);
    k_stage1 <<<dim3(4, Bb*Ff, 4),  64>>>(Kl, Ml);
    k_stage2 <<<dim3(Bb*Ff, 2),    384>>>();
    k_solver <<<Bb,             SOLV_T>>>(u0, Wf1, Wf2, Wz, bfv);
    k_ufine  <<<dim3(Nn/128, Bb),  128>>>(out);
}

// round 15
// speedup vs baseline: 1.9846x; 1.0747x over previous
#include <cuda_runtime.h>
#include <math.h>

#define Bb   16
#define Nn   1024
#define DIN  32
#define DZ   64
#define DH   64
#define Ff   3
#define Pp   19
#define PPAD 20
#define NEDGE 171
#define ITERS 50
#define ALPHAc 0.1f
#define INV_SCALE (19.0f/1024.0f)
#define SCTA   2          // cluster CTAs per batch
#define SOLV_T 384

// ---------------- device scratch (static; no allocations) ----------------
__device__ __align__(16) float2 g_wpair[(size_t)Bb*Ff*Nn*PPAD]; // {w,w} pairs for FFMA2 (stage1)
__device__ __align__(16) float  g_wc[(size_t)Bb*Ff*Nn*PPAD];    // compact weights (stage2/ufine)
__device__ __align__(16) float  g_t[(size_t)192*Pp*Nn];         // stage-1 partials
__device__ __align__(16) float  g_khat[2*Bb*Ff*Pp*Pp];          // [mat][b][f][p][q]
__device__ __align__(16) float  g_zpart[Bb*8*DZ];               // per-block z partial sums
__device__ __align__(16) float  g_flpart[Bb*8*64];              // per-block f_latent partials
__device__ __align__(16) float  g_uhat[Bb*64];

// packed f32x2 FMA (Blackwell FFMA2)
__device__ __forceinline__ unsigned long long ffma2(unsigned long long a,
                                                    unsigned long long b,
                                                    unsigned long long c) {
    unsigned long long d;
    asm("fma.rn.f32x2 %0, %1, %2, %3;" : "=l"(d) : "l"(a), "l"(b), "l"(c));
    return d;
}
__device__ __forceinline__ float2 ull2f2(unsigned long long v) {
    float2 r;
    asm("mov.b64 {%0,%1}, %2;" : "=f"(r.x), "=f"(r.y) : "l"(v));
    return r;
}
__device__ __forceinline__ unsigned long long packdup(float v) {
    unsigned long long r;
    asm("mov.b64 %0, {%1,%1};" : "=l"(r) : "f"(v));
    return r;
}
__device__ __forceinline__ unsigned long long pack2(float a, float b) {
    unsigned long long r;
    asm("mov.b64 %0, {%1,%2};" : "=l"(r) : "f"(a), "f"(b));
    return r;
}
__device__ __forceinline__ float warp_sum(float v) {
    v += __shfl_xor_sync(0xffffffffu, v, 16);
    v += __shfl_xor_sync(0xffffffffu, v, 8);
    v += __shfl_xor_sync(0xffffffffu, v, 4);
    v += __shfl_xor_sync(0xffffffffu, v, 2);
    v += __shfl_xor_sync(0xffffffffu, v, 1);
    return v;
}
__device__ __forceinline__ float tanh_fast(float x) {
    float r;
    asm("tanh.approx.f32 %0, %1;" : "=f"(r) : "f"(x));
    return r;
}
__device__ __forceinline__ unsigned int smem_u32(const void* p) {
    unsigned int a;
    asm("{ .reg .u64 t; cvta.to.shared.u64 t, %1; cvt.u32.u64 %0, t; }" : "=r"(a) : "l"(p));
    return a;
}
__device__ __forceinline__ void sts_remote(unsigned int addr, unsigned int rank, float v) {
    asm volatile("{ .reg .b32 r; mapa.shared::cluster.u32 r, %0, %1; "
                 "st.shared::cluster.f32 [r], %2; }"
                 :: "r"(addr), "r"(rank), "f"(v) : "memory");
}
#define CLUSTER_SYNC() do { \
    asm volatile("barrier.cluster.arrive.aligned;" ::: "memory"); \
    asm volatile("barrier.cluster.wait.aligned;"   ::: "memory"); } while (0)

// ---------------- kernel 1: encoder + POU softmax + fused partial reductions ----------------
__global__ __launch_bounds__(128) void k_encode(
    const float* __restrict__ tok, const int* __restrict__ dn,
    const float* __restrict__ bv,
    const float* __restrict__ W_enc, const float* __restrict__ b_enc,
    const float* __restrict__ W_src, const float* __restrict__ b_src,
    const float* __restrict__ W_pou)
{
    __shared__ float sWe[DIN*DZ];
    __shared__ float sWp[DZ*57];
    __shared__ float sWs[DZ*Ff];
    __shared__ float sbe[DZ];
    __shared__ float sbs[Ff];
    __shared__ int   sdn[64];
    __shared__ float sbv[64*Ff];
    __shared__ float sW4[4][DZ];
    __shared__ float sFl[4][Pp];

    int b = blockIdx.y;
    int tid = threadIdx.x;
    int wid = tid >> 5, lane = tid & 31;
    for (int i = tid; i < DIN*DZ; i += 128) sWe[i] = W_enc[i];
    for (int i = tid; i < DZ*57;  i += 128) sWp[i] = W_pou[i];
    for (int i = tid; i < DZ*Ff;  i += 128) sWs[i] = W_src[i];
    if (tid < DZ) sbe[tid] = b_enc[tid];
    if (tid < Ff) sbs[tid] = b_src[tid];
    if (tid < 64) sdn[tid] = dn[b*64 + tid];
    for (int i = tid; i < 64*Ff; i += 128) sbv[i] = bv[b*64*Ff + i];
    __syncthreads();

    int n = blockIdx.x*128 + tid;

    float x[DIN];
    const float4* xp = (const float4*)(tok + ((size_t)b*Nn + n)*DIN);
    #pragma unroll
    for (int i = 0; i < DIN/4; i++) {
        float4 v = xp[i];
        x[4*i] = v.x; x[4*i+1] = v.y; x[4*i+2] = v.z; x[4*i+3] = v.w;
    }

    float z[DZ];
    #pragma unroll
    for (int d = 0; d < DZ; d++) z[d] = sbe[d];
    for (int k = 0; k < DIN; k++) {
        float xv = x[k];
        const float* wr = sWe + k*DZ;
        #pragma unroll
        for (int d = 0; d < DZ; d++) z[d] += xv * wr[d];
    }
    #pragma unroll
    for (int d = 0; d < DZ; d++) z[d] = tanh_fast(z[d]);

    // z-mean partial (deterministic fixed reduction order)
    #pragma unroll
    for (int d = 0; d < DZ; d++) {
        float v = warp_sum(z[d]);
        if (lane == 0) sW4[wid][d] = v;
    }
    __syncthreads();
    if (tid < DZ)
        g_zpart[((size_t)b*8 + blockIdx.x)*DZ + tid] =
            sW4[0][tid] + sW4[1][tid] + sW4[2][tid] + sW4[3][tid];

    // f_full
    float ffull[Ff];
    #pragma unroll
    for (int f = 0; f < Ff; f++) {
        float s = sbs[f];
        for (int d = 0; d < DZ; d++) s += z[d]*sWs[d*Ff + f];
        ffull[f] = s;
    }

    // boundary value scatter (last occurrence wins, matching JAX .set)
    float bvv[Ff] = {0.f, 0.f, 0.f};
    for (int k = 0; k < 64; k++) {
        if (sdn[k] == n) {
            bvv[0] = sbv[k*Ff]; bvv[1] = sbv[k*Ff+1]; bvv[2] = sbv[k*Ff+2];
        }
    }

    // softmax over P per field + weight stores + f_latent partials
    for (int f = 0; f < Ff; f++) {
        float lg[Pp];
        #pragma unroll
        for (int p = 0; p < Pp; p++) {
            float s = 0.f;
            for (int d = 0; d < DZ; d++) s += z[d]*sWp[d*57 + p*Ff + f];
            lg[p] = s;
        }
        lg[16] += bvv[f]; lg[17] += bvv[f]; lg[18] += bvv[f];
        float m = lg[0];
        #pragma unroll
        for (int p = 1; p < Pp; p++) m = fmaxf(m, lg[p]);
        float s = 0.f;
        #pragma unroll
        for (int p = 0; p < Pp; p++) { lg[p] = __expf(lg[p]-m); s += lg[p]; }
        float inv = 1.f/s;
        float2* wp = g_wpair + ((size_t)(b*Ff + f)*Nn + n)*PPAD;
        float*  wc = g_wc    + ((size_t)(b*Ff + f)*Nn + n)*PPAD;
        #pragma unroll
        for (int p = 0; p < Pp; p++) {
            float w = lg[p]*inv;
            lg[p] = w;
            wp[p] = make_float2(w, w);
            wc[p] = w;
        }
        __syncthreads();
        #pragma unroll
        for (int p = 0; p < Pp; p++) {
            float v = warp_sum(lg[p]*ffull[f]);
            if (lane == 0) sFl[wid][p] = v;
        }
        __syncthreads();
        if (tid < Pp)
            g_flpart[((size_t)b*8 + blockIdx.x)*64 + tid*Ff + f] =
                sFl[0][tid] + sFl[1][tid] + sFl[2][tid] + sFl[3][tid];
    }
}

// ------------- kernel 2: stage-1 projection  t[p,j] = sum_i W[p,i]*A[i,j] -------------
__global__ __launch_bounds__(64) void k_stage1(const float* __restrict__ Kl,
                                               const float* __restrict__ Ml)
{
    int bf   = blockIdx.y;
    int mat  = blockIdx.z >> 1;
    int half = blockIdx.z & 1;
    int j0   = blockIdx.x*256 + threadIdx.x*4;

    const float* src = (mat ? Ml : Kl) + (size_t)bf*Nn*Nn;
    const unsigned long long* wsrc =
        (const unsigned long long*)(g_wpair + (size_t)bf*Nn*PPAD);

    __shared__ __align__(16) unsigned long long sw[32*PPAD];

    unsigned long long acc[2*Pp];
    #pragma unroll
    for (int i = 0; i < 2*Pp; i++) acc[i] = 0ull;

    for (int ic = 0; ic < 16; ic++) {
        int ib = half*512 + ic*32;
        const unsigned long long* g = wsrc + (size_t)ib*PPAD;
        for (int idx = threadIdx.x; idx < 32*PPAD; idx += 64) sw[idx] = g[idx];
        __syncthreads();
        const float* kptr = src + (size_t)ib*Nn + j0;
        #pragma unroll 4
        for (int ii = 0; ii < 32; ii++) {
            float4 kv = *(const float4*)kptr;
            unsigned long long kx = pack2(kv.x, kv.y);
            unsigned long long ky = pack2(kv.z, kv.w);
            kptr += Nn;
            const unsigned long long* wrow = sw + ii*PPAD;
            #pragma unroll
            for (int pp = 0; pp < 9; pp++) {       // vectorized w reads: LDS.128
                ulonglong2 wv = *(const ulonglong2*)(wrow + 2*pp);
                acc[4*pp+0] = ffma2(wv.x, kx, acc[4*pp+0]);
                acc[4*pp+1] = ffma2(wv.x, ky, acc[4*pp+1]);
                acc[4*pp+2] = ffma2(wv.y, kx, acc[4*pp+2]);
                acc[4*pp+3] = ffma2(wv.y, ky, acc[4*pp+3]);
            }
            unsigned long long w18 = wrow[18];
            acc[36] = ffma2(w18, kx, acc[36]);
            acc[37] = ffma2(w18, ky, acc[37]);
        }
        __syncthreads();
    }

    float* tp = g_t + ((size_t)((bf*2 + mat)*2 + half))*Pp*Nn;
    #pragma unroll
    for (int p = 0; p < Pp; p++) {
        float2 a0 = ull2f2(acc[2*p]);
        float2 a1 = ull2f2(acc[2*p+1]);
        *(float4*)(tp + p*Nn + j0) = make_float4(a0.x, a0.y, a1.x, a1.y);
    }
}

// ------------- stage-2: K_hat[p,q] = (t W^T)/scale + Dirichlet rows -------------
__global__ __launch_bounds__(384) void k_stage2()
{
    int bf = blockIdx.x;
    int mat = blockIdx.y;
    __shared__ float tS[Pp][129];
    __shared__ float wS[128*PPAD];
    int t = threadIdx.x;
    int p = t % Pp, q = t / Pp;
    bool act = (t < Pp*Pp);
    float acc = 0.f;
    const float* t0 = g_t + (size_t)((bf*2 + mat)*2)*Pp*Nn;
    const float* t1 = t0 + Pp*Nn;
    const float* wsrc0 = g_wc + (size_t)bf*Nn*PPAD;
    for (int jc = 0; jc < 8; jc++) {
        for (int idx = t; idx < Pp*128; idx += 384) {
            int pp = idx >> 7, jj = idx & 127;
            tS[pp][jj] = t0[pp*Nn + jc*128 + jj] + t1[pp*Nn + jc*128 + jj];
        }
        const float* wsrc = wsrc0 + (size_t)jc*128*PPAD;
        for (int idx = t; idx < 128*PPAD; idx += 384) wS[idx] = wsrc[idx];
        __syncthreads();
        if (act) {
            #pragma unroll 8
            for (int jj = 0; jj < 128; jj++) acc += tS[p][jj]*wS[jj*PPAD + q];
        }
        __syncthreads();
    }
    if (act) {
        float v = acc * INV_SCALE;
        if (p >= Pp-3) v = (p == q) ? 1.f : 0.f;
        g_khat[((size_t)mat*Bb*Ff + bf)*Pp*Pp + p*Pp + q] = v;
    }
}

// ------------- solver: 2-CTA cluster per batch, DSMEM flux exchange -------------
// CTA rank r owns 86/85 edges; flux thread t = edge_local*4 + qt, 8 h-pairs
// each (FFMA2, bank-padded weight slices, zp/c01/c2 register-cached).
// Fluxes are written to BOTH CTAs' smem (double-buffered by iteration parity
// -> write-after-read across iterations cannot race). One barrier.cluster per
// iteration orders the exchange; the residual update runs redundantly in both
// CTAs (u stays CTA-local).
__global__ __launch_bounds__(SOLV_T, 1) __cluster_dims__(SCTA, 1, 1)
void k_solver(const float* __restrict__ u_init,
              const float* __restrict__ Wf1,
              const float* __restrict__ Wf2,
              const float* __restrict__ Wz,
              const float* __restrict__ bfv)
{
    int rank = blockIdx.x & (SCTA-1);
    int b    = blockIdx.x / SCTA;
    int t    = threadIdx.x;
    __shared__ float Ks[Ff*Pp*Pp];
    __shared__ __align__(16) unsigned long long w1s[4*66];
    __shared__ __align__(16) unsigned long long w2s[4*34];
    __shared__ float srcs[64];
    __shared__ __align__(16) float flux[2][NEDGE*4];
    __shared__ float ua[64], ub[64];
    __shared__ float mz[DZ];
    __shared__ float sfl[64];

    for (int i = t; i < Ff*Pp*Pp; i += SOLV_T)
        Ks[i] = g_khat[(size_t)b*Ff*Pp*Pp + i];
    if (t < DH) {  // scatter Wf1/Wf2 into padded per-qt h-pair slices
        int h = t, hpg = h >> 1, par = h & 1;
        int qts = hpg >> 3, hpl = hpg & 7;
        float* w1f = (float*)w1s;
        float* w2f = (float*)w2s;
        int b1 = (qts*66 + hpl*8)*2 + par;
        w1f[b1 + 0]  = Wf1[0*DH + h];
        w1f[b1 + 2]  = Wf1[1*DH + h];
        w1f[b1 + 4]  = Wf1[2*DH + h];
        w1f[b1 + 6]  = Wf1[3*DH + h];
        w1f[b1 + 8]  = Wf1[4*DH + h];
        w1f[b1 + 10] = Wf1[5*DH + h];
        w1f[b1 + 14] = 0.f;
        int b2 = (qts*34 + hpl*4)*2 + par;
        w2f[b2 + 0] = Wf2[h*Ff + 0];
        w2f[b2 + 2] = Wf2[h*Ff + 1];
        w2f[b2 + 4] = Wf2[h*Ff + 2];
        w2f[b2 + 6] = 0.f;
    }
    if (t < Pp*Ff) ua[t] = u_init[b*Pp*Ff + t];
    if (t < DZ) {
        float s = 0.f;
        #pragma unroll
        for (int k = 0; k < 8; k++) s += g_zpart[((size_t)b*8 + k)*DZ + t];
        mz[t] = s * (1.f/Nn);
    } else if (t >= 64 && t < 64 + Pp*Ff) {
        int k = t - 64;
        float s = 0.f;
        #pragma unroll
        for (int j = 0; j < 8; j++) s += g_flpart[((size_t)b*8 + j)*64 + k];
        sfl[k] = s * INV_SCALE;
    }
    __syncthreads();

    if (t < DH) {  // zp = mean(z) @ Wz + bf  -> slot 6 of the h-pair record
        float a = bfv[t];
        #pragma unroll 8
        for (int d = 0; d < DZ; d++) a += mz[d]*Wz[d*DH + t];
        int h = t, hpg = h >> 1, par = h & 1;
        int qts = hpg >> 3, hpl = hpg & 7;
        ((float*)w1s)[(qts*66 + hpl*8)*2 + 12 + par] = a;
    } else if (t >= 64 && t < 64 + Pp*Ff) {  // src_term = M_hat @ f_latent
        int k = t - 64;
        int p = k / Ff, f = k % Ff;
        const float* mrow = g_khat + ((size_t)Bb*Ff + b*Ff + f)*Pp*Pp + p*Pp;
        float s = 0.f;
        #pragma unroll
        for (int q = 0; q < Pp; q++) s += mrow[q]*sfl[q*Ff + f];
        srcs[k] = s;
    }

    // edge mapping for this CTA (warps stay converged: clamp, guard the write)
    int el = t >> 2;
    int qt = t & 3;
    int ecnt = (rank == 0) ? 86 : (NEDGE - 86);
    int ge = rank*86 + ((el < ecnt) ? el : 0);
    bool wr = (qt == 0) && (el < ecnt);
    int ei, ej;
    {
        int ee = ge, a = 0;
        while (ee >= Pp-1-a) { ee -= (Pp-1-a); a++; }
        ei = a; ej = a + 1 + ee;
    }
    const unsigned long long* w1u = w1s + qt*66;
    const unsigned long long* w2u = w2s + qt*34;

    // residual-update mapping (4-way split, t<256, warps converged via clamp)
    int k2 = t >> 2; if (k2 > 56) k2 = 56;
    int sub = t & 3;
    int p2 = k2 / Ff, f2 = k2 % Ff;
    __syncthreads();

    // register-cache loop-invariant weights (zp, c0/c1 pair, c2)
    ulonglong2 c01r[8];
    unsigned long long zpr[8], c2r[8];
    #pragma unroll
    for (int hp = 0; hp < 8; hp++) {
        c01r[hp] = *(const ulonglong2*)(w2u + hp*4);
        c2r[hp]  = w2u[hp*4 + 2];
        zpr[hp]  = w1u[hp*8 + 6];
    }
    unsigned int peer = rank ^ 1;

    CLUSTER_SYNC();   // peer smem ready before any remote flux write

    float* cur = ua; float* nxt = ub;
    for (int it = 0; it < ITERS; it++) {
        float* fb = flux[it & 1];
        {
            unsigned long long up0 = packdup(cur[ei*Ff+0]);
            unsigned long long up1 = packdup(cur[ei*Ff+1]);
            unsigned long long up2 = packdup(cur[ei*Ff+2]);
            unsigned long long up3 = packdup(cur[ej*Ff+0]);
            unsigned long long up4 = packdup(cur[ej*Ff+1]);
            unsigned long long up5 = packdup(cur[ej*Ff+2]);
            unsigned long long acc0 = 0ull, acc1 = 0ull, acc2 = 0ull;
            #pragma unroll
            for (int hp = 0; hp < 8; hp++) {
                const unsigned long long* r1 = w1u + hp*8;
                ulonglong2 a01 = *(const ulonglong2*)(r1);
                ulonglong2 a23 = *(const ulonglong2*)(r1 + 2);
                ulonglong2 a45 = *(const ulonglong2*)(r1 + 4);
                unsigned long long s = zpr[hp];
                s = ffma2(up0, a01.x, s);
                s = ffma2(up1, a01.y, s);
                s = ffma2(up2, a23.x, s);
                s = ffma2(up3, a23.y, s);
                s = ffma2(up4, a45.x, s);
                s = ffma2(up5, a45.y, s);
                float2 sv = ull2f2(s);
                unsigned long long rp = pack2(tanh_fast(sv.x), tanh_fast(sv.y));
                acc0 = ffma2(rp, c01r[hp].x, acc0);
                acc1 = ffma2(rp, c01r[hp].y, acc1);
                acc2 = ffma2(rp, c2r[hp],    acc2);
            }
            float2 f0 = ull2f2(acc0), f1 = ull2f2(acc1), f2v = ull2f2(acc2);
            float a0 = f0.x + f0.y, a1 = f1.x + f1.y, a2 = f2v.x + f2v.y;
            a0 += __shfl_xor_sync(0xffffffffu, a0, 1);
            a0 += __shfl_xor_sync(0xffffffffu, a0, 2);
            a1 += __shfl_xor_sync(0xffffffffu, a1, 1);
            a1 += __shfl_xor_sync(0xffffffffu, a1, 2);
            a2 += __shfl_xor_sync(0xffffffffu, a2, 1);
            a2 += __shfl_xor_sync(0xffffffffu, a2, 2);
            if (wr) {
                int base = ge*4;
                fb[base+0] = a0; fb[base+1] = a1; fb[base+2] = a2;
                unsigned int ra = smem_u32(fb + base);
                sts_remote(ra + 0, peer, a0);
                sts_remote(ra + 4, peer, a1);
                sts_remote(ra + 8, peer, a2);
            }
        }
        CLUSTER_SYNC();   // all 171 fluxes visible in both CTAs
        if (t < 256) {    // redundant 4-way-split residual update
            const float* kr = Ks + f2*Pp*Pp + p2*Pp;
            float part = 0.f;
            #pragma unroll
            for (int q = sub; q < Pp; q += 4) part += kr[q]*cur[q*Ff + f2];
            #pragma unroll
            for (int idx = sub; idx < Pp-1; idx += 4) {
                int q = idx + (idx >= p2 ? 1 : 0);
                if (q < p2) {
                    int ee = q*(Pp-1) - (q*(q-1))/2 + (p2 - q - 1);
                    part -= fb[ee*4 + f2];
                } else {
                    int ee = p2*(Pp-1) - (p2*(p2-1))/2 + (q - p2 - 1);
                    part += fb[ee*4 + f2];
                }
            }
            part += __shfl_xor_sync(0xffffffffu, part, 1);
            part += __shfl_xor_sync(0xffffffffu, part, 2);
            if (sub == 0) {
                float r = part - srcs[k2];
                if (p2 >= Pp-3) r = cur[k2] - ((p2 == Pp-3) ? 1.f : 0.f);
                nxt[k2] = cur[k2] - ALPHAc*r;
            }
        }
        __syncthreads();
        float* tmp = cur; cur = nxt; nxt = tmp;
    }
    if (rank == 0 && t < Pp*Ff) g_uhat[b*64 + t] = cur[t];
}

// ------------- u_fine = W^T u_coarse (compact weights, vectorized) -------------
__global__ __launch_bounds__(128) void k_ufine(float* __restrict__ out)
{
    int b = blockIdx.y;
    int tid = threadIdx.x;
    int n = blockIdx.x*128 + tid;
    __shared__ float us[64];
    __shared__ __align__(16) float so[384];
    if (tid < 64) us[tid] = g_uhat[b*64 + tid];
    __syncthreads();
    float o[Ff];
    #pragma unroll
    for (int f = 0; f < Ff; f++) {
        const float4* wv = (const float4*)(g_wc + ((size_t)(b*Ff + f)*Nn + n)*PPAD);
        float acc = 0.f;
        #pragma unroll
        for (int k = 0; k < 5; k++) {
            float4 w4 = wv[k];
            int p0 = 4*k;
            acc += w4.x*us[p0*Ff + f];
            if (p0+1 < Pp) acc += w4.y*us[(p0+1)*Ff + f];
            if (p0+2 < Pp) acc += w4.z*us[(p0+2)*Ff + f];
            if (p0+3 < Pp) acc += w4.w*us[(p0+3)*Ff + f];
        }
        o[f] = acc;
    }
    so[tid*3+0] = o[0]; so[tid*3+1] = o[1]; so[tid*3+2] = o[2];
    __syncthreads();
    float4* ob = (float4*)(out + ((size_t)b*Nn + blockIdx.x*128)*Ff);
    if (tid < 96) ob[tid] = ((const float4*)so)[tid];
}

// ---------------- launch ----------------
extern "C" void kernel_launch(void* const* d_in, const int* in_sizes, int n_in,
                              void* d_out, int out_size)
{
    const float* tok   = (const float*)d_in[0];
    const float* Kl    = (const float*)d_in[1];
    const float* Ml    = (const float*)d_in[2];
    const int*   dn    = (const int*)  d_in[3];
    const float* bv    = (const float*)d_in[4];
    const float* u0    = (const float*)d_in[5];
    const float* W_enc = (const float*)d_in[6];
    const float* b_enc = (const float*)d_in[7];
    const float* W_src = (const float*)d_in[8];
    const float* b_src = (const float*)d_in[9];
    const float* W_pou = (const float*)d_in[10];
    const float* Wf1   = (const float*)d_in[11];
    const float* Wz    = (const float*)d_in[12];
    const float* bfv   = (const float*)d_in[13];
    const float* Wf2   = (const float*)d_in[14];
    float* out = (float*)d_out;

    k_encode <<<dim3(Nn/128, Bb),  128>>>(tok, dn, bv, W_enc, b_enc, W_src, b_src, W_pou);
    k_stage1 <<<dim3(4, Bb*Ff, 4),  64>>>(Kl, Ml);
    k_stage2 <<<dim3(Bb*Ff, 2),    384>>>();
    k_solver <<<Bb*SCTA,        SOLV_T>>>(u0, Wf1, Wf2, Wz, bfv);
    k_ufine  <<<dim3(Nn/128, Bb),  128>>>(out);
}